// round 1
// baseline (speedup 1.0000x reference)
#include <cuda_runtime.h>
#include <cfloat>

#define NPTS 4096
#define MQ   1024
#define CCH  64

__global__ __launch_bounds__(256, 4)
void maxpool_box_kernel(const float* __restrict__ values,
                        const float* __restrict__ coords,
                        const float* __restrict__ qcoords,
                        float* __restrict__ out) {
    __shared__ int   s_idx[NPTS];
    __shared__ int   s_count;
    __shared__ float s_red[4][CCH];

    const int q   = blockIdx.x;
    const int tid = threadIdx.x;

    const float qx = qcoords[2 * q];
    const float qy = qcoords[2 * q + 1];

    if (tid == 0) s_count = 0;
    __syncthreads();

    // Phase 1: build candidate list (indices of points inside the box)
    const float2* __restrict__ c2 = (const float2*)coords;
    #pragma unroll 4
    for (int i = tid; i < NPTS; i += 256) {
        float2 c = c2[i];
        if (fabsf(qx - c.x) < 0.05f && fabsf(qy - c.y) < 0.05f) {
            int p = atomicAdd(&s_count, 1);
            s_idx[p] = i;
        }
    }
    __syncthreads();

    const int cnt   = s_count;
    const int ch    = tid & (CCH - 1);   // channel 0..63
    const int slice = tid >> 6;          // candidate slice 0..3

    // Phase 2: gather-max over matched rows. 64 consecutive channels per row
    // -> fully coalesced 256B reads; 4 slices give point-level parallelism.
    float m = -FLT_MAX;
    for (int j = slice; j < cnt; j += 4) {
        m = fmaxf(m, values[s_idx[j] * CCH + ch]);
    }
    s_red[slice][ch] = m;
    __syncthreads();

    // Reduce 4 slices, write out
    if (tid < CCH) {
        float r = fmaxf(fmaxf(s_red[0][tid], s_red[1][tid]),
                        fmaxf(s_red[2][tid], s_red[3][tid]));
        out[q * CCH + tid] = r;
    }
}

extern "C" void kernel_launch(void* const* d_in, const int* in_sizes, int n_in,
                              void* d_out, int out_size) {
    const float* values  = (const float*)d_in[0];   // [N, C] f32
    const float* coords  = (const float*)d_in[1];   // [N, 2] f32
    const float* qcoords = (const float*)d_in[2];   // [M, 2] f32
    float* out = (float*)d_out;                     // [M, C] f32

    maxpool_box_kernel<<<MQ, 256>>>(values, coords, qcoords, out);
}